// round 14
// baseline (speedup 1.0000x reference)
#include <cuda_runtime.h>
#include <cuda_fp16.h>
#include <cstdint>
#include <cstring>

#define BBATCH 2
#define SEQ 2048
#define DMODEL 1024
#define NH 16
#define HD 64
#define MROWS (BBATCH*SEQ)
#define NELEM (MROWS*DMODEL)
#define WELEM (DMODEL*DMODEL)

// ---------------- scratch (static device globals) --------------------------
__device__ __half g_wq[WELEM], g_wk[WELEM], g_wv[WELEM], g_wo[WELEM];
__device__ __half g_Qh[NELEM], g_Kh[NELEM], g_Vh[NELEM];
__device__ __half g_AOh[NELEM];

// ---------------- PTX helpers ---------------------------------------------
__device__ __forceinline__ uint32_t cvta_s(const void* p) {
    return (uint32_t)__cvta_generic_to_shared(p);
}
__device__ __forceinline__ void ldmx4(uint32_t* r, uint32_t a) {
    asm volatile("ldmatrix.sync.aligned.m8n8.x4.shared.b16 {%0,%1,%2,%3}, [%4];"
        : "=r"(r[0]), "=r"(r[1]), "=r"(r[2]), "=r"(r[3]) : "r"(a));
}
__device__ __forceinline__ void ldmx4t(uint32_t* r, uint32_t a) {
    asm volatile("ldmatrix.sync.aligned.m8n8.x4.trans.shared.b16 {%0,%1,%2,%3}, [%4];"
        : "=r"(r[0]), "=r"(r[1]), "=r"(r[2]), "=r"(r[3]) : "r"(a));
}
__device__ __forceinline__ void mma16816(float* d, const uint32_t* a, const uint32_t* b) {
    asm volatile("mma.sync.aligned.m16n8k16.row.col.f32.f16.f16.f32 "
        "{%0,%1,%2,%3}, {%4,%5,%6,%7}, {%8,%9}, {%0,%1,%2,%3};"
        : "+f"(d[0]), "+f"(d[1]), "+f"(d[2]), "+f"(d[3])
        : "r"(a[0]), "r"(a[1]), "r"(a[2]), "r"(a[3]), "r"(b[0]), "r"(b[1]));
}
__device__ __forceinline__ uint32_t packh2(float x, float y) {
    __half2 h = __floats2half2_rn(x, y);
    uint32_t u; memcpy(&u, &h, 4);
    return u;
}
__device__ __forceinline__ void cp16(uint32_t dst, const void* src) {
    asm volatile("cp.async.cg.shared.global [%0], [%1], 16;" :: "r"(dst), "l"(src));
}
__device__ __forceinline__ void cp_commit() {
    asm volatile("cp.async.commit_group;" ::: "memory");
}
__device__ __forceinline__ void cp_wait0() {
    asm volatile("cp.async.wait_group 0;" ::: "memory");
}

// epilogue store helpers
__device__ __forceinline__ void st2(__half* C, size_t off, float a, float b) {
    *(__half2*)(C + off) = __floats2half2_rn(a, b);
}
__device__ __forceinline__ void st2(float* C, size_t off, float a, float b) {
    *(float2*)(C + off) = make_float2(a, b);
}

// compact B smem addressing: 2 logical rows per 128B physical row.
__device__ __forceinline__ uint32_t baddr(int r, int ch) {
    return (uint32_t)(((r >> 1) * 128) +
                      ((((r & 1) * 4 + ch) ^ ((r >> 1) & 7)) * 16));
}

// ---------------- weight convert: 4 weights in one launch -------------------
__global__ void __launch_bounds__(256) convert_w4(
    const float* __restrict__ s0, const float* __restrict__ s1,
    const float* __restrict__ s2, const float* __restrict__ s3,
    __half* __restrict__ d0, __half* __restrict__ d1,
    __half* __restrict__ d2, __half* __restrict__ d3, int n4)
{
    int z = blockIdx.y;
    const float* X = (z == 0) ? s0 : (z == 1) ? s1 : (z == 2) ? s2 : s3;
    __half* Y = (z == 0) ? d0 : (z == 1) ? d1 : (z == 2) ? d2 : d3;
    int i = blockIdx.x * blockDim.x + threadIdx.x;
    if (i < n4) {
        float4 v = ((const float4*)X)[i];
        uint2 u;
        u.x = packh2(v.x, v.y);
        u.y = packh2(v.z, v.w);
        ((uint2*)Y)[i] = u;
    }
}

// ---------------- GEMM compute slice: 64x32 warp tile, k32 ------------------
// sA: 128 rows x 128B, hi chunks 0-3, XOR-swizzled by row&7. sB: compact 8KB.
__device__ __forceinline__ void tile_compute32(
    uint32_t sAu, uint32_t sBu, int wm, int wn, int lane, float acc[4][4][4])
{
#pragma unroll
    for (int s = 0; s < 2; ++s) {
        uint32_t ah[4][4];
#pragma unroll
        for (int mt = 0; mt < 4; ++mt) {
            int row = wm * 64 + mt * 16 + (lane & 15);
            int ch = s * 2 + (lane >> 4);
            ldmx4(ah[mt], sAu + row * 128 + ((ch ^ (row & 7)) * 16));
        }
        uint32_t bh[4][2];
#pragma unroll
        for (int p = 0; p < 2; ++p) {
            int g = lane >> 3;
            int nrow = wn * 32 + p * 16 + (g & 2) * 4 + (lane & 7);
            int ch = s * 2 + (g & 1);
            uint32_t t[4];
            ldmx4(t, sBu + baddr(nrow, ch));
            bh[2 * p][0] = t[0]; bh[2 * p][1] = t[1];
            bh[2 * p + 1][0] = t[2]; bh[2 * p + 1][1] = t[3];
        }
#pragma unroll
        for (int mt = 0; mt < 4; ++mt)
#pragma unroll
            for (int nt = 0; nt < 4; ++nt)
                mma16816(acc[mt][nt], ah[mt], bh[nt]);
    }
}

template<typename OutT>
__device__ __forceinline__ void gemm_epilogue32(
    float acc[4][4][4], const float* bias, OutT* C,
    int bm, int bn, int wm, int wn, int lane)
{
    const int gr = lane >> 2, ct = lane & 3;
#pragma unroll
    for (int mt = 0; mt < 4; ++mt)
#pragma unroll
        for (int nt = 0; nt < 4; ++nt) {
            size_t row = bm + wm * 64 + mt * 16 + gr;
            int col = bn + wn * 32 + nt * 8 + ct * 2;
            float b0 = bias[col], b1 = bias[col + 1];
            st2(C, row * DMODEL + col, acc[mt][nt][0] + b0, acc[mt][nt][1] + b1);
            st2(C, (row + 8) * DMODEL + col, acc[mt][nt][2] + b0, acc[mt][nt][3] + b1);
        }
}

// ---------------- GEMM, A fp32 (QKV): R8 shape --------------------------------
// CTA 128x128, 256 thr (2x4 warps, 64x32 tiles). Double-buffered, 1 barrier/k32.
__device__ __forceinline__ void gemm_f32A_core(
    const float* __restrict__ A, const __half* __restrict__ Wh,
    const float* __restrict__ bias, __half* __restrict__ C)
{
    __shared__ alignas(16) char sA[2][16384];
    __shared__ alignas(16) char sB[2][8192];
    const uint32_t sA0 = cvta_s(sA), sB0 = cvta_s(sB);

    const int tid = threadIdx.x;
    const int lane = tid & 31;
    const int wid = tid >> 5;
    const int wm = wid >> 2, wn = wid & 3;
    const int bm = blockIdx.y * 128, bn = blockIdx.x * 128;

    const int r0 = tid >> 3;     // rows r0 + i*32
    const int c4 = tid & 7;      // float4 column
    const float* Ap = A + (size_t)(bm + r0) * DMODEL + c4 * 4;

    const int wrow = tid >> 1;
    const int wch0 = (tid & 1) * 2;
    const __half* Wp = Wh + (size_t)(bn + wrow) * DMODEL + wch0 * 8;

    float4 ra[4];
    float4 rw0, rw1;
    auto ldg_tile = [&](int it) {
        const float* Ap2 = Ap + it * 32;
        const __half* Wp2 = Wp + it * 32;
#pragma unroll
        for (int i = 0; i < 4; ++i)
            ra[i] = *(const float4*)(Ap2 + (size_t)i * 32 * DMODEL);
        rw0 = *(const float4*)(Wp2);
        rw1 = *(const float4*)(Wp2 + 8);
    };
    auto store_tile = [&](int st) {
#pragma unroll
        for (int i = 0; i < 4; ++i) {
            int row = r0 + i * 32;
            int hch = (c4 >> 1) ^ (row & 7);
            int sub = (c4 & 1) * 8;
            uint2 hi;
            hi.x = packh2(ra[i].x, ra[i].y);
            hi.y = packh2(ra[i].z, ra[i].w);
            *(uint2*)(sA[st] + row * 128 + hch * 16 + sub) = hi;
        }
        *(float4*)(sB[st] + baddr(wrow, wch0)) = rw0;
        *(float4*)(sB[st] + baddr(wrow, wch0 + 1)) = rw1;
    };

    float acc[4][4][4];
#pragma unroll
    for (int mt = 0; mt < 4; ++mt)
#pragma unroll
        for (int nt = 0; nt < 4; ++nt)
#pragma unroll
            for (int e = 0; e < 4; ++e) acc[mt][nt][e] = 0.f;

    ldg_tile(0);
    store_tile(0);
    ldg_tile(1);
    __syncthreads();

    for (int it = 0; it < 32; ++it) {
        const int cur = it & 1;
        if (it < 31) store_tile(cur ^ 1);
        tile_compute32(sA0 + cur * 16384, sB0 + cur * 8192, wm, wn, lane, acc);
        if (it < 30) ldg_tile(it + 2);
        __syncthreads();
    }
    gemm_epilogue32<__half>(acc, bias, C, bm, bn, wm, wn, lane);
}

// merged Q/K/V projection (single-pass fp16)
__global__ void __launch_bounds__(256) gemm_qkv(
    const float* q, const float* k, const float* v,
    const __half* wq, const __half* wk, const __half* wv,
    const float* bq, const float* bk, const float* bv,
    __half* Qh, __half* Kh, __half* Vh)
{
    int z = blockIdx.z;
    const float* A = (z == 0) ? q : (z == 1) ? k : v;
    const __half* W = (z == 0) ? wq : (z == 1) ? wk : wv;
    const float* b = (z == 0) ? bq : (z == 1) ? bk : bv;
    __half* C = (z == 0) ? Qh : (z == 1) ? Kh : Vh;
    gemm_f32A_core(A, W, b, C);
}

// ---------------- GEMM, A fp16 (out-proj): same R8 shape --------------------
__global__ void __launch_bounds__(256) gemm_out_f16A(
    const __half* __restrict__ A, const __half* __restrict__ Wh,
    const float* __restrict__ bias, float* __restrict__ C)
{
    __shared__ alignas(16) char sA[2][16384];
    __shared__ alignas(16) char sB[2][8192];
    const uint32_t sA0 = cvta_s(sA), sB0 = cvta_s(sB);

    const int tid = threadIdx.x;
    const int lane = tid & 31;
    const int wid = tid >> 5;
    const int wm = wid >> 2, wn = wid & 3;
    const int bm = blockIdx.y * 128, bn = blockIdx.x * 128;

    const int r0 = tid >> 3;
    const int c4 = tid & 7;    // 4-half (8B) column within 32-k slice
    const __half* Ap = A + (size_t)(bm + r0) * DMODEL + c4 * 4;

    const int wrow = tid >> 1;
    const int wch0 = (tid & 1) * 2;
    const __half* Wp = Wh + (size_t)(bn + wrow) * DMODEL + wch0 * 8;

    uint2 ra[4];
    float4 rw0, rw1;
    auto ldg_tile = [&](int it) {
        const __half* Ap2 = Ap + it * 32;
        const __half* Wp2 = Wp + it * 32;
#pragma unroll
        for (int i = 0; i < 4; ++i)
            ra[i] = *(const uint2*)(Ap2 + (size_t)i * 32 * DMODEL);
        rw0 = *(const float4*)(Wp2);
        rw1 = *(const float4*)(Wp2 + 8);
    };
    auto store_tile = [&](int st) {
#pragma unroll
        for (int i = 0; i < 4; ++i) {
            int row = r0 + i * 32;
            int hch = (c4 >> 1) ^ (row & 7);
            int sub = (c4 & 1) * 8;
            *(uint2*)(sA[st] + row * 128 + hch * 16 + sub) = ra[i];
        }
        *(float4*)(sB[st] + baddr(wrow, wch0)) = rw0;
        *(float4*)(sB[st] + baddr(wrow, wch0 + 1)) = rw1;
    };

    float acc[4][4][4];
#pragma unroll
    for (int mt = 0; mt < 4; ++mt)
#pragma unroll
        for (int nt = 0; nt < 4; ++nt)
#pragma unroll
            for (int e = 0; e < 4; ++e) acc[mt][nt][e] = 0.f;

    ldg_tile(0);
    store_tile(0);
    ldg_tile(1);
    __syncthreads();

    for (int it = 0; it < 32; ++it) {
        const int cur = it & 1;
        if (it < 31) store_tile(cur ^ 1);
        tile_compute32(sA0 + cur * 16384, sB0 + cur * 8192, wm, wn, lane, acc);
        if (it < 30) ldg_tile(it + 2);
        __syncthreads();
    }
    gemm_epilogue32<float>(acc, bias, C, bm, bn, wm, wn, lane);
}

// ---------------- fp16 flash attention (causal), cp.async pipeline ----------
__global__ void __launch_bounds__(128) attn_fp16(
    const __half* __restrict__ Q, const __half* __restrict__ K,
    const __half* __restrict__ V, __half* __restrict__ AO)
{
    __shared__ alignas(16) char sK[2][64 * 128];
    __shared__ alignas(16) char sV[2][64 * 128];
    const uint32_t sK0 = cvta_s(sK), sV0 = cvta_s(sV);

    const int tid = threadIdx.x;
    const int lane = tid & 31;
    const int w = tid >> 5;
    const int qt = (int)gridDim.x - 1 - (int)blockIdx.x;
    const int bh = blockIdx.y;
    const int b = bh >> 4, h = bh & 15;

    const size_t base = (size_t)b * SEQ * DMODEL + (size_t)h * HD;

    const int lr = tid >> 3;
    const int c4 = tid & 7;

    {
        const __half* Qp = Q + base + (size_t)(qt * 64) * DMODEL;
#pragma unroll
        for (int i = 0; i < 4; ++i) {
            int row = lr + i * 16;
            float4 v = *(const float4*)(Qp + (size_t)row * DMODEL + c4 * 8);
            *(float4*)(sK[0] + row * 128 + ((c4 ^ (row & 7)) * 16)) = v;
        }
    }
    __syncthreads();

    uint32_t qf[4][4];
#pragma unroll
    for (int s = 0; s < 4; ++s) {
        int row = w * 16 + (lane & 15);
        int ch = 2 * s + (lane >> 4);
        ldmx4(qf[s], sK0 + row * 128 + ((ch ^ (row & 7)) * 16));
    }
    __syncthreads();

    float oacc[8][4];
#pragma unroll
    for (int dt = 0; dt < 8; ++dt)
#pragma unroll
        for (int e = 0; e < 4; ++e) oacc[dt][e] = 0.f;
    float m0 = -1e30f, m1 = -1e30f, l0 = 0.f, l1 = 0.f;

    const __half* Kp = K + base;
    const __half* Vp = V + base;

    {
#pragma unroll
        for (int i = 0; i < 4; ++i) {
            int row = lr + i * 16;
            uint32_t off = row * 128 + ((c4 ^ (row & 7)) * 16);
            cp16(sK0 + off, Kp + (size_t)row * DMODEL + c4 * 8);
            cp16(sV0 + off, Vp + (size_t)row * DMODEL + c4 * 8);
        }
        cp_commit();
    }

    for (int kt = 0; kt <= qt; ++kt) {
        cp_wait0();
        __syncthreads();
        if (kt < qt) {
            int st = (kt + 1) & 1;
            const __half* ks = Kp + (size_t)((kt + 1) * 64) * DMODEL;
            const __half* vs = Vp + (size_t)((kt + 1) * 64) * DMODEL;
#pragma unroll
            for (int i = 0; i < 4; ++i) {
                int row = lr + i * 16;
                uint32_t off = row * 128 + ((c4 ^ (row & 7)) * 16);
                cp16(sK0 + st * 8192 + off, ks + (size_t)row * DMODEL + c4 * 8);
                cp16(sV0 + st * 8192 + off, vs + (size_t)row * DMODEL + c4 * 8);
            }
            cp_commit();
        }
        const uint32_t sKu = sK0 + (kt & 1) * 8192;
        const uint32_t sVu = sV0 + (kt & 1) * 8192;

        float sacc[8][4];
#pragma unroll
        for (int nt = 0; nt < 8; ++nt)
#pragma unroll
            for (int e = 0; e < 4; ++e) sacc[nt][e] = 0.f;

#pragma unroll
        for (int s = 0; s < 4; ++s) {
            uint32_t kb[8][2];
#pragma unroll
            for (int p = 0; p < 4; ++p) {
                int g = lane >> 3;
                int nrow = p * 16 + (g & 2) * 4 + (lane & 7);
                int ch = 2 * s + (g & 1);
                uint32_t t[4];
                ldmx4(t, sKu + nrow * 128 + ((ch ^ (nrow & 7)) * 16));
                kb[2 * p][0] = t[0]; kb[2 * p][1] = t[1];
                kb[2 * p + 1][0] = t[2]; kb[2 * p + 1][1] = t[3];
            }
#pragma unroll
            for (int nt = 0; nt < 8; ++nt)
                mma16816(sacc[nt], qf[s], kb[nt]);
        }

        const bool diag = (kt == qt);
        const int rq0 = w * 16 + (lane >> 2);
        const int cl0 = (lane & 3) * 2;
#pragma unroll
        for (int nt = 0; nt < 8; ++nt)
#pragma unroll
            for (int e = 0; e < 4; ++e) {
                float vv = sacc[nt][e] * 0.125f;
                if (diag) {
                    int cc = nt * 8 + cl0 + (e & 1);
                    int qq = rq0 + (e >> 1) * 8;
                    if (cc > qq) vv = -1e30f;
                }
                sacc[nt][e] = vv;
            }

        float t0 = -1e30f, t1 = -1e30f;
#pragma unroll
        for (int nt = 0; nt < 8; ++nt) {
            t0 = fmaxf(t0, fmaxf(sacc[nt][0], sacc[nt][1]));
            t1 = fmaxf(t1, fmaxf(sacc[nt][2], sacc[nt][3]));
        }
        t0 = fmaxf(t0, __shfl_xor_sync(0xffffffffu, t0, 1));
        t0 = fmaxf(t0, __shfl_xor_sync(0xffffffffu, t0, 2));
        t1 = fmaxf(t1, __shfl_xor_sync(0xffffffffu, t1, 1));
        t1 = fmaxf(t1, __shfl_xor_sync(0xffffffffu, t1, 2));
        float mn0 = fmaxf(m0, t0), mn1 = fmaxf(m1, t1);
        float corr0 = __expf(m0 - mn0), corr1 = __expf(m1 - mn1);
        m0 = mn0; m1 = mn1;

        float rs0 = 0.f, rs1 = 0.f;
#pragma unroll
        for (int nt = 0; nt < 8; ++nt) {
            sacc[nt][0] = __expf(sacc[nt][0] - mn0);
            sacc[nt][1] = __expf(sacc[nt][1] - mn0);
            sacc[nt][2] = __expf(sacc[nt][2] - mn1);
            sacc[nt][3] = __expf(sacc[nt][3] - mn1);
            rs0 += sacc[nt][0] + sacc[nt][1];
            rs1 += sacc[nt][2] + sacc[nt][3];
        }
        rs0 += __shfl_xor_sync(0xffffffffu, rs0, 1);
        rs0 += __shfl_xor_sync(0xffffffffu, rs0, 2);
        rs1 += __shfl_xor_sync(0xffffffffu, rs1, 1);
        rs1 += __shfl_xor_sync(0xffffffffu, rs1, 2);
        l0 = l0 * corr0 + rs0;
        l1 = l1 * corr1 + rs1;
#pragma unroll
        for (int dt = 0; dt < 8; ++dt) {
            oacc[dt][0] *= corr0; oacc[dt][1] *= corr0;
            oacc[dt][2] *= corr1; oacc[dt][3] *= corr1;
        }

#pragma unroll
        for (int s = 0; s < 4; ++s) {
            uint32_t af[4];
            af[0] = packh2(sacc[2 * s][0], sacc[2 * s][1]);
            af[1] = packh2(sacc[2 * s][2], sacc[2 * s][3]);
            af[2] = packh2(sacc[2 * s + 1][0], sacc[2 * s + 1][1]);
            af[3] = packh2(sacc[2 * s + 1][2], sacc[2 * s + 1][3]);
            uint32_t vb[8][2];
#pragma unroll
            for (int p = 0; p < 4; ++p) {
                int g = lane >> 3;
                int vrow = s * 16 + (g & 1) * 8 + (lane & 7);
                int ch = p * 2 + (g >> 1);
                uint32_t t[4];
                ldmx4t(t, sVu + vrow * 128 + ((ch ^ (vrow & 7)) * 16));
                vb[2 * p][0] = t[0]; vb[2 * p][1] = t[1];
                vb[2 * p + 1][0] = t[2]; vb[2 * p + 1][1] = t[3];
            }
#pragma unroll
            for (int dt = 0; dt < 8; ++dt)
                mma16816(oacc[dt], af, vb[dt]);
        }
    }

    // epilogue: write O directly as fp16 (out-proj consumes fp16 anyway)
    float i0 = 1.f / l0, i1 = 1.f / l1;
    const int gr = lane >> 2, ct2 = (lane & 3) * 2;
    __half* Op = AO + (size_t)b * SEQ * DMODEL + (size_t)h * HD;
    size_t rowq = qt * 64 + w * 16 + gr;
#pragma unroll
    for (int dt = 0; dt < 8; ++dt) {
        int col = dt * 8 + ct2;
        *(__half2*)(Op + rowq * DMODEL + col) =
            __floats2half2_rn(oacc[dt][0] * i0, oacc[dt][1] * i0);
        *(__half2*)(Op + (rowq + 8) * DMODEL + col) =
            __floats2half2_rn(oacc[dt][2] * i1, oacc[dt][3] * i1);
    }
}

// ---------------- launch ---------------------------------------------------
extern "C" void kernel_launch(void* const* d_in, const int* in_sizes, int n_in,
                              void* d_out, int out_size)
{
    const float* q    = (const float*)d_in[0];
    const float* k    = (const float*)d_in[1];
    const float* v    = (const float*)d_in[2];
    // d_in[3]: causal mask (tril) — applied analytically
    const float* wq_w = (const float*)d_in[4];
    const float* wq_b = (const float*)d_in[5];
    const float* wk_w = (const float*)d_in[6];
    const float* wk_b = (const float*)d_in[7];
    const float* wv_w = (const float*)d_in[8];
    const float* wv_b = (const float*)d_in[9];
    const float* wo_w = (const float*)d_in[10];
    const float* wo_b = (const float*)d_in[11];
    float* out = (float*)d_out;

    __half *wq, *wk, *wv, *wo, *Qh, *Kh, *Vh, *AOh;
    cudaGetSymbolAddress((void**)&wq, g_wq);
    cudaGetSymbolAddress((void**)&wk, g_wk);
    cudaGetSymbolAddress((void**)&wv, g_wv);
    cudaGetSymbolAddress((void**)&wo, g_wo);
    cudaGetSymbolAddress((void**)&Qh, g_Qh);
    cudaGetSymbolAddress((void**)&Kh, g_Kh);
    cudaGetSymbolAddress((void**)&Vh, g_Vh);
    cudaGetSymbolAddress((void**)&AOh, g_AOh);

    const int n4w = WELEM / 4;
    convert_w4<<<dim3(n4w / 256, 4), 256>>>(wq_w, wk_w, wv_w, wo_w,
                                            wq, wk, wv, wo, n4w);

    dim3 gqkv(DMODEL / 128, MROWS / 128, 3);   // (8, 32, 3) = 768 CTAs
    gemm_qkv<<<gqkv, 256>>>(q, k, v, wq, wk, wv, wq_b, wk_b, wv_b, Qh, Kh, Vh);

    attn_fp16<<<dim3(SEQ / 64, BBATCH * NH), 128>>>(Qh, Kh, Vh, AOh);

    dim3 gb(DMODEL / 128, MROWS / 128);        // (8, 32) = 256 CTAs
    gemm_out_f16A<<<gb, 256>>>(AOh, wo, wo_b, out);
}

// round 16
// speedup vs baseline: 1.0235x; 1.0235x over previous
#include <cuda_runtime.h>
#include <cuda_fp16.h>
#include <cstdint>
#include <cstring>

#define BBATCH 2
#define SEQ 2048
#define DMODEL 1024
#define NH 16
#define HD 64
#define MROWS (BBATCH*SEQ)
#define NELEM (MROWS*DMODEL)
#define WELEM (DMODEL*DMODEL)

// ---------------- scratch (static device globals) --------------------------
__device__ __half g_wq[WELEM], g_wk[WELEM], g_wv[WELEM], g_wo[WELEM];
__device__ __half g_qa[NELEM], g_ka[NELEM], g_va[NELEM];
__device__ __half g_Qh[NELEM], g_Kh[NELEM], g_Vh[NELEM];
__device__ __half g_AOh[NELEM];

// ---------------- PTX helpers ---------------------------------------------
__device__ __forceinline__ uint32_t cvta_s(const void* p) {
    return (uint32_t)__cvta_generic_to_shared(p);
}
__device__ __forceinline__ void ldmx4(uint32_t* r, uint32_t a) {
    asm volatile("ldmatrix.sync.aligned.m8n8.x4.shared.b16 {%0,%1,%2,%3}, [%4];"
        : "=r"(r[0]), "=r"(r[1]), "=r"(r[2]), "=r"(r[3]) : "r"(a));
}
__device__ __forceinline__ void ldmx4t(uint32_t* r, uint32_t a) {
    asm volatile("ldmatrix.sync.aligned.m8n8.x4.trans.shared.b16 {%0,%1,%2,%3}, [%4];"
        : "=r"(r[0]), "=r"(r[1]), "=r"(r[2]), "=r"(r[3]) : "r"(a));
}
__device__ __forceinline__ void mma16816(float* d, const uint32_t* a, const uint32_t* b) {
    asm volatile("mma.sync.aligned.m16n8k16.row.col.f32.f16.f16.f32 "
        "{%0,%1,%2,%3}, {%4,%5,%6,%7}, {%8,%9}, {%0,%1,%2,%3};"
        : "+f"(d[0]), "+f"(d[1]), "+f"(d[2]), "+f"(d[3])
        : "r"(a[0]), "r"(a[1]), "r"(a[2]), "r"(a[3]), "r"(b[0]), "r"(b[1]));
}
__device__ __forceinline__ uint32_t packh2(float x, float y) {
    __half2 h = __floats2half2_rn(x, y);
    uint32_t u; memcpy(&u, &h, 4);
    return u;
}
__device__ __forceinline__ void cp16(uint32_t dst, const void* src) {
    asm volatile("cp.async.cg.shared.global [%0], [%1], 16;" :: "r"(dst), "l"(src));
}
__device__ __forceinline__ void cp_commit() {
    asm volatile("cp.async.commit_group;" ::: "memory");
}
__device__ __forceinline__ void cp_wait0() {
    asm volatile("cp.async.wait_group 0;" ::: "memory");
}

// epilogue store helpers
__device__ __forceinline__ void st2(__half* C, size_t off, float a, float b) {
    *(__half2*)(C + off) = __floats2half2_rn(a, b);
}
__device__ __forceinline__ void st2(float* C, size_t off, float a, float b) {
    *(float2*)(C + off) = make_float2(a, b);
}

// ---------------- converts --------------------------------------------------
__global__ void __launch_bounds__(256) convert_w4(
    const float* __restrict__ s0, const float* __restrict__ s1,
    const float* __restrict__ s2, const float* __restrict__ s3,
    __half* __restrict__ d0, __half* __restrict__ d1,
    __half* __restrict__ d2, __half* __restrict__ d3, int n4)
{
    int z = blockIdx.y;
    const float* X = (z == 0) ? s0 : (z == 1) ? s1 : (z == 2) ? s2 : s3;
    __half* Y = (z == 0) ? d0 : (z == 1) ? d1 : (z == 2) ? d2 : d3;
    int i = blockIdx.x * blockDim.x + threadIdx.x;
    if (i < n4) {
        float4 v = ((const float4*)X)[i];
        uint2 u;
        u.x = packh2(v.x, v.y);
        u.y = packh2(v.z, v.w);
        ((uint2*)Y)[i] = u;
    }
}
__global__ void __launch_bounds__(256) convert_a3(
    const float* __restrict__ s0, const float* __restrict__ s1,
    const float* __restrict__ s2,
    __half* __restrict__ d0, __half* __restrict__ d1,
    __half* __restrict__ d2, int n4)
{
    int z = blockIdx.y;
    const float* X = (z == 0) ? s0 : (z == 1) ? s1 : s2;
    __half* Y = (z == 0) ? d0 : (z == 1) ? d1 : d2;
    int i = blockIdx.x * blockDim.x + threadIdx.x;
    if (i < n4) {
        float4 v = ((const float4*)X)[i];
        uint2 u;
        u.x = packh2(v.x, v.y);
        u.y = packh2(v.z, v.w);
        ((uint2*)Y)[i] = u;
    }
}

// ---------------- BK=64 GEMM: C = A*W^T + bias ------------------------------
// CTA 128x128, 256 thr (2x4 warps, 64x32 tiles). A,W fp16, all cp.async.
// Stage = A[128][64h] + B[128][64h], each row 128B, chunks 0..7 XOR row&7.
// Double buffer, one barrier per k64 (16 iterations).
#define G64_STAGE 16384
#define G64_SMEM (4 * G64_STAGE)   // sA[2] + sB[2] = 64KB dynamic

__device__ __forceinline__ void tile_compute64(
    uint32_t sAu, uint32_t sBu, int wm, int wn, int lane, float acc[4][4][4])
{
#pragma unroll
    for (int s = 0; s < 4; ++s) {
        uint32_t ah[4][4];
#pragma unroll
        for (int mt = 0; mt < 4; ++mt) {
            int row = wm * 64 + mt * 16 + (lane & 15);
            int ch = s * 2 + (lane >> 4);
            ldmx4(ah[mt], sAu + row * 128 + ((ch ^ (row & 7)) * 16));
        }
        uint32_t bh[4][2];
#pragma unroll
        for (int p = 0; p < 2; ++p) {
            int g = lane >> 3;
            int nrow = wn * 32 + p * 16 + (g & 2) * 4 + (lane & 7);
            int ch = s * 2 + (g & 1);
            uint32_t t[4];
            ldmx4(t, sBu + nrow * 128 + ((ch ^ (nrow & 7)) * 16));
            bh[2 * p][0] = t[0]; bh[2 * p][1] = t[1];
            bh[2 * p + 1][0] = t[2]; bh[2 * p + 1][1] = t[3];
        }
#pragma unroll
        for (int mt = 0; mt < 4; ++mt)
#pragma unroll
            for (int nt = 0; nt < 4; ++nt)
                mma16816(acc[mt][nt], ah[mt], bh[nt]);
    }
}

template<typename OutT>
__device__ __forceinline__ void gemm64_core(
    const __half* __restrict__ A, const __half* __restrict__ Wh,
    const float* __restrict__ bias, OutT* __restrict__ C)
{
    extern __shared__ char smem[];
    const uint32_t sA0 = cvta_s(smem);
    const uint32_t sB0 = sA0 + 2 * G64_STAGE;

    const int tid = threadIdx.x;
    const int lane = tid & 31;
    const int wid = tid >> 5;
    const int wm = wid >> 2, wn = wid & 3;
    const int bm = blockIdx.y * 128, bn = blockIdx.x * 128;

    const int row = tid >> 1;       // 0..127
    const int hf = tid & 1;         // half of the 64-k slice
    const __half* Ap = A + (size_t)(bm + row) * DMODEL + hf * 32;
    const __half* Wp = Wh + (size_t)(bn + row) * DMODEL + hf * 32;

    auto cpAW = [&](int st, int it) {
        uint32_t sa = sA0 + st * G64_STAGE;
        uint32_t sw = sB0 + st * G64_STAGE;
        const __half* a2 = Ap + it * 64;
        const __half* w2 = Wp + it * 64;
#pragma unroll
        for (int q = 0; q < 4; ++q) {
            int ch = hf * 4 + q;
            uint32_t so = row * 128 + ((ch ^ (row & 7)) * 16);
            cp16(sa + so, a2 + q * 8);
            cp16(sw + so, w2 + q * 8);
        }
    };

    float acc[4][4][4];
#pragma unroll
    for (int mt = 0; mt < 4; ++mt)
#pragma unroll
        for (int nt = 0; nt < 4; ++nt)
#pragma unroll
            for (int e = 0; e < 4; ++e) acc[mt][nt][e] = 0.f;

    cpAW(0, 0); cp_commit();
    cp_wait0();
    __syncthreads();

    for (int it = 0; it < 16; ++it) {
        const int cur = it & 1;
        if (it < 15) { cpAW(cur ^ 1, it + 1); cp_commit(); }
        tile_compute64(sA0 + cur * G64_STAGE, sB0 + cur * G64_STAGE,
                       wm, wn, lane, acc);
        if (it < 15) cp_wait0();
        __syncthreads();
    }

    const int gr = lane >> 2, ct = lane & 3;
#pragma unroll
    for (int mt = 0; mt < 4; ++mt)
#pragma unroll
        for (int nt = 0; nt < 4; ++nt) {
            size_t r = bm + wm * 64 + mt * 16 + gr;
            int col = bn + wn * 32 + nt * 8 + ct * 2;
            float b0 = bias[col], b1 = bias[col + 1];
            st2(C, r * DMODEL + col, acc[mt][nt][0] + b0, acc[mt][nt][1] + b1);
            st2(C, (r + 8) * DMODEL + col, acc[mt][nt][2] + b0, acc[mt][nt][3] + b1);
        }
}

__global__ void __launch_bounds__(256, 2) gemm_qkv64(
    const __half* qa, const __half* ka, const __half* va,
    const __half* wq, const __half* wk, const __half* wv,
    const float* bq, const float* bk, const float* bv,
    __half* Qh, __half* Kh, __half* Vh)
{
    int z = blockIdx.z;
    const __half* A = (z == 0) ? qa : (z == 1) ? ka : va;
    const __half* W = (z == 0) ? wq : (z == 1) ? wk : wv;
    const float* b = (z == 0) ? bq : (z == 1) ? bk : bv;
    __half* C = (z == 0) ? Qh : (z == 1) ? Kh : Vh;
    gemm64_core<__half>(A, W, b, C);
}

__global__ void __launch_bounds__(256, 2) gemm_out64(
    const __half* __restrict__ A, const __half* __restrict__ Wh,
    const float* __restrict__ bias, float* __restrict__ C)
{
    gemm64_core<float>(A, Wh, bias, C);
}

// ---------------- fp16 flash attention (causal), cp.async pipeline ----------
__global__ void __launch_bounds__(128) attn_fp16(
    const __half* __restrict__ Q, const __half* __restrict__ K,
    const __half* __restrict__ V, __half* __restrict__ AO)
{
    __shared__ alignas(16) char sK[2][64 * 128];
    __shared__ alignas(16) char sV[2][64 * 128];
    const uint32_t sK0 = cvta_s(sK), sV0 = cvta_s(sV);

    const int tid = threadIdx.x;
    const int lane = tid & 31;
    const int w = tid >> 5;
    const int qt = (int)gridDim.x - 1 - (int)blockIdx.x;
    const int bh = blockIdx.y;
    const int b = bh >> 4, h = bh & 15;

    const size_t base = (size_t)b * SEQ * DMODEL + (size_t)h * HD;

    const int lr = tid >> 3;
    const int c4 = tid & 7;

    {
        const __half* Qp = Q + base + (size_t)(qt * 64) * DMODEL;
#pragma unroll
        for (int i = 0; i < 4; ++i) {
            int row = lr + i * 16;
            float4 v = *(const float4*)(Qp + (size_t)row * DMODEL + c4 * 8);
            *(float4*)(sK[0] + row * 128 + ((c4 ^ (row & 7)) * 16)) = v;
        }
    }
    __syncthreads();

    uint32_t qf[4][4];
#pragma unroll
    for (int s = 0; s < 4; ++s) {
        int row = w * 16 + (lane & 15);
        int ch = 2 * s + (lane >> 4);
        ldmx4(qf[s], sK0 + row * 128 + ((ch ^ (row & 7)) * 16));
    }
    __syncthreads();

    float oacc[8][4];
#pragma unroll
    for (int dt = 0; dt < 8; ++dt)
#pragma unroll
        for (int e = 0; e < 4; ++e) oacc[dt][e] = 0.f;
    float m0 = -1e30f, m1 = -1e30f, l0 = 0.f, l1 = 0.f;

    const __half* Kp = K + base;
    const __half* Vp = V + base;

    {
#pragma unroll
        for (int i = 0; i < 4; ++i) {
            int row = lr + i * 16;
            uint32_t off = row * 128 + ((c4 ^ (row & 7)) * 16);
            cp16(sK0 + off, Kp + (size_t)row * DMODEL + c4 * 8);
            cp16(sV0 + off, Vp + (size_t)row * DMODEL + c4 * 8);
        }
        cp_commit();
    }

    for (int kt = 0; kt <= qt; ++kt) {
        cp_wait0();
        __syncthreads();
        if (kt < qt) {
            int st = (kt + 1) & 1;
            const __half* ks = Kp + (size_t)((kt + 1) * 64) * DMODEL;
            const __half* vs = Vp + (size_t)((kt + 1) * 64) * DMODEL;
#pragma unroll
            for (int i = 0; i < 4; ++i) {
                int row = lr + i * 16;
                uint32_t off = row * 128 + ((c4 ^ (row & 7)) * 16);
                cp16(sK0 + st * 8192 + off, ks + (size_t)row * DMODEL + c4 * 8);
                cp16(sV0 + st * 8192 + off, vs + (size_t)row * DMODEL + c4 * 8);
            }
            cp_commit();
        }
        const uint32_t sKu = sK0 + (kt & 1) * 8192;
        const uint32_t sVu = sV0 + (kt & 1) * 8192;

        float sacc[8][4];
#pragma unroll
        for (int nt = 0; nt < 8; ++nt)
#pragma unroll
            for (int e = 0; e < 4; ++e) sacc[nt][e] = 0.f;

#pragma unroll
        for (int s = 0; s < 4; ++s) {
            uint32_t kb[8][2];
#pragma unroll
            for (int p = 0; p < 4; ++p) {
                int g = lane >> 3;
                int nrow = p * 16 + (g & 2) * 4 + (lane & 7);
                int ch = 2 * s + (g & 1);
                uint32_t t[4];
                ldmx4(t, sKu + nrow * 128 + ((ch ^ (nrow & 7)) * 16));
                kb[2 * p][0] = t[0]; kb[2 * p][1] = t[1];
                kb[2 * p + 1][0] = t[2]; kb[2 * p + 1][1] = t[3];
            }
#pragma unroll
            for (int nt = 0; nt < 8; ++nt)
                mma16816(sacc[nt], qf[s], kb[nt]);
        }

        const bool diag = (kt == qt);
        const int rq0 = w * 16 + (lane >> 2);
        const int cl0 = (lane & 3) * 2;
#pragma unroll
        for (int nt = 0; nt < 8; ++nt)
#pragma unroll
            for (int e = 0; e < 4; ++e) {
                float vv = sacc[nt][e] * 0.125f;
                if (diag) {
                    int cc = nt * 8 + cl0 + (e & 1);
                    int qq = rq0 + (e >> 1) * 8;
                    if (cc > qq) vv = -1e30f;
                }
                sacc[nt][e] = vv;
            }

        float t0 = -1e30f, t1 = -1e30f;
#pragma unroll
        for (int nt = 0; nt < 8; ++nt) {
            t0 = fmaxf(t0, fmaxf(sacc[nt][0], sacc[nt][1]));
            t1 = fmaxf(t1, fmaxf(sacc[nt][2], sacc[nt][3]));
        }
        t0 = fmaxf(t0, __shfl_xor_sync(0xffffffffu, t0, 1));
        t0 = fmaxf(t0, __shfl_xor_sync(0xffffffffu, t0, 2));
        t1 = fmaxf(t1, __shfl_xor_sync(0xffffffffu, t1, 1));
        t1 = fmaxf(t1, __shfl_xor_sync(0xffffffffu, t1, 2));
        float mn0 = fmaxf(m0, t0), mn1 = fmaxf(m1, t1);
        float corr0 = __expf(m0 - mn0), corr1 = __expf(m1 - mn1);
        m0 = mn0; m1 = mn1;

        float rs0 = 0.f, rs1 = 0.f;
#pragma unroll
        for (int nt = 0; nt < 8; ++nt) {
            sacc[nt][0] = __expf(sacc[nt][0] - mn0);
            sacc[nt][1] = __expf(sacc[nt][1] - mn0);
            sacc[nt][2] = __expf(sacc[nt][2] - mn1);
            sacc[nt][3] = __expf(sacc[nt][3] - mn1);
            rs0 += sacc[nt][0] + sacc[nt][1];
            rs1 += sacc[nt][2] + sacc[nt][3];
        }
        rs0 += __shfl_xor_sync(0xffffffffu, rs0, 1);
        rs0 += __shfl_xor_sync(0xffffffffu, rs0, 2);
        rs1 += __shfl_xor_sync(0xffffffffu, rs1, 1);
        rs1 += __shfl_xor_sync(0xffffffffu, rs1, 2);
        l0 = l0 * corr0 + rs0;
        l1 = l1 * corr1 + rs1;
#pragma unroll
        for (int dt = 0; dt < 8; ++dt) {
            oacc[dt][0] *= corr0; oacc[dt][1] *= corr0;
            oacc[dt][2] *= corr1; oacc[dt][3] *= corr1;
        }

#pragma unroll
        for (int s = 0; s < 4; ++s) {
            uint32_t af[4];
            af[0] = packh2(sacc[2 * s][0], sacc[2 * s][1]);
            af[1] = packh2(sacc[2 * s][2], sacc[2 * s][3]);
            af[2] = packh2(sacc[2 * s + 1][0], sacc[2 * s + 1][1]);
            af[3] = packh2(sacc[2 * s + 1][2], sacc[2 * s + 1][3]);
            uint32_t vb[8][2];
#pragma unroll
            for (int p = 0; p < 4; ++p) {
                int g = lane >> 3;
                int vrow = s * 16 + (g & 1) * 8 + (lane & 7);
                int ch = p * 2 + (g >> 1);
                uint32_t t[4];
                ldmx4t(t, sVu + vrow * 128 + ((ch ^ (vrow & 7)) * 16));
                vb[2 * p][0] = t[0]; vb[2 * p][1] = t[1];
                vb[2 * p + 1][0] = t[2]; vb[2 * p + 1][1] = t[3];
            }
#pragma unroll
            for (int dt = 0; dt < 8; ++dt)
                mma16816(oacc[dt], af, vb[dt]);
        }
    }

    float i0 = 1.f / l0, i1 = 1.f / l1;
    const int gr = lane >> 2, ct2 = (lane & 3) * 2;
    __half* Op = AO + (size_t)b * SEQ * DMODEL + (size_t)h * HD;
    size_t rowq = qt * 64 + w * 16 + gr;
#pragma unroll
    for (int dt = 0; dt < 8; ++dt) {
        int col = dt * 8 + ct2;
        *(__half2*)(Op + rowq * DMODEL + col) =
            __floats2half2_rn(oacc[dt][0] * i0, oacc[dt][1] * i0);
        *(__half2*)(Op + (rowq + 8) * DMODEL + col) =
            __floats2half2_rn(oacc[dt][2] * i1, oacc[dt][3] * i1);
    }
}

// ---------------- launch ---------------------------------------------------
extern "C" void kernel_launch(void* const* d_in, const int* in_sizes, int n_in,
                              void* d_out, int out_size)
{
    const float* q    = (const float*)d_in[0];
    const float* k    = (const float*)d_in[1];
    const float* v    = (const float*)d_in[2];
    // d_in[3]: causal mask (tril) — applied analytically
    const float* wq_w = (const float*)d_in[4];
    const float* wq_b = (const float*)d_in[5];
    const float* wk_w = (const float*)d_in[6];
    const float* wk_b = (const float*)d_in[7];
    const float* wv_w = (const float*)d_in[8];
    const float* wv_b = (const float*)d_in[9];
    const float* wo_w = (const float*)d_in[10];
    const float* wo_b = (const float*)d_in[11];
    float* out = (float*)d_out;

    __half *wq, *wk, *wv, *wo, *qa, *ka, *va, *Qh, *Kh, *Vh, *AOh;
    cudaGetSymbolAddress((void**)&wq, g_wq);
    cudaGetSymbolAddress((void**)&wk, g_wk);
    cudaGetSymbolAddress((void**)&wv, g_wv);
    cudaGetSymbolAddress((void**)&wo, g_wo);
    cudaGetSymbolAddress((void**)&qa, g_qa);
    cudaGetSymbolAddress((void**)&ka, g_ka);
    cudaGetSymbolAddress((void**)&va, g_va);
    cudaGetSymbolAddress((void**)&Qh, g_Qh);
    cudaGetSymbolAddress((void**)&Kh, g_Kh);
    cudaGetSymbolAddress((void**)&Vh, g_Vh);
    cudaGetSymbolAddress((void**)&AOh, g_AOh);

    cudaFuncSetAttribute(gemm_qkv64,
                         cudaFuncAttributeMaxDynamicSharedMemorySize, G64_SMEM);
    cudaFuncSetAttribute(gemm_out64,
                         cudaFuncAttributeMaxDynamicSharedMemorySize, G64_SMEM);

    const int n4w = WELEM / 4, n4a = NELEM / 4;
    convert_w4<<<dim3(n4w / 256, 4), 256>>>(wq_w, wk_w, wv_w, wo_w,
                                            wq, wk, wv, wo, n4w);
    convert_a3<<<dim3(n4a / 256, 3), 256>>>(q, k, v, qa, ka, va, n4a);

    dim3 gqkv(DMODEL / 128, MROWS / 128, 3);   // (8, 32, 3)
    gemm_qkv64<<<gqkv, 256, G64_SMEM>>>(qa, ka, va, wq, wk, wv,
                                        wq_b, wk_b, wv_b, Qh, Kh, Vh);

    attn_fp16<<<dim3(SEQ / 64, BBATCH * NH), 128>>>(Qh, Kh, Vh, AOh);

    dim3 gb(DMODEL / 128, MROWS / 128);        // (8, 32)
    gemm_out64<<<gb, 256, G64_SMEM>>>(AOh, wo, wo_b, out);
}